// round 3
// baseline (speedup 1.0000x reference)
#include <cuda_runtime.h>
#include <math.h>

#define Bsz 2
#define Tt  2048
#define Cc  1024
#define Hh  16
#define DHd 64
#define Mrows (Bsz*Tt)   // 4096

// Scratch (allocation-free: __device__ globals)
__device__ float g_q[(size_t)Bsz*Hh*Tt*DHd];   // [B,H,T,Dh]
__device__ float g_k[(size_t)Bsz*Hh*Tt*DHd];
__device__ float g_v[(size_t)Bsz*Hh*Tt*DHd];
__device__ float g_att[(size_t)Bsz*Tt*Cc];     // [B,T,C]

// ---------------------------------------------------------------------------
// Tiled GEMM: C[M,N] = A[M,1024] @ B[1024,N] + bias
// BM=BN=64, BK=16, 256 threads, 4x4 register tile per thread.
// MODE 0: plain write to Cout
// MODE 1: scatter into g_q/g_k/g_v with [B,H,T,Dh] layout
// MODE 2: like MODE 0 but A comes from g_att (device global)
// ---------------------------------------------------------------------------
template <int MODE>
__global__ __launch_bounds__(256)
void gemm_kernel(const float* __restrict__ A, const float* __restrict__ Bw,
                 const float* __restrict__ bias, float* __restrict__ Cout, int N)
{
    __shared__ float As[16 * 65];   // [k][m], pitch 65 (conflict-free transposed stores)
    __shared__ float Bs[16 * 64];   // [k][n]

    const float* Aptr = (MODE == 2) ? g_att : A;

    const int tx = threadIdx.x, ty = threadIdx.y;
    const int tid = ty * 16 + tx;
    const int m0 = blockIdx.y * 64, n0 = blockIdx.x * 64;
    const int K = Cc;

    float acc[4][4];
#pragma unroll
    for (int r = 0; r < 4; r++)
#pragma unroll
        for (int c = 0; c < 4; c++) acc[r][c] = 0.0f;

    const int am = tid >> 2;          // 0..63
    const int ak = (tid & 3) * 4;     // 0,4,8,12
    const int bk = tid >> 4;          // 0..15
    const int bn = (tid & 15) * 4;    // 0..60

    for (int k0 = 0; k0 < K; k0 += 16) {
        // A tile (64m x 16k) -> As[k][m]
        float4 va = *(const float4*)(Aptr + (size_t)(m0 + am) * K + k0 + ak);
        As[(ak + 0) * 65 + am] = va.x;
        As[(ak + 1) * 65 + am] = va.y;
        As[(ak + 2) * 65 + am] = va.z;
        As[(ak + 3) * 65 + am] = va.w;
        // B tile (16k x 64n) -> Bs[k][n]
        float4 vb = *(const float4*)(Bw + (size_t)(k0 + bk) * N + n0 + bn);
        *(float4*)(Bs + bk * 64 + bn) = vb;
        __syncthreads();

#pragma unroll
        for (int kk = 0; kk < 16; kk++) {
            float a0 = As[kk * 65 + ty * 4 + 0];
            float a1 = As[kk * 65 + ty * 4 + 1];
            float a2 = As[kk * 65 + ty * 4 + 2];
            float a3 = As[kk * 65 + ty * 4 + 3];
            float4 b4 = *(const float4*)(Bs + kk * 64 + tx * 4);
            acc[0][0] += a0 * b4.x; acc[0][1] += a0 * b4.y; acc[0][2] += a0 * b4.z; acc[0][3] += a0 * b4.w;
            acc[1][0] += a1 * b4.x; acc[1][1] += a1 * b4.y; acc[1][2] += a1 * b4.z; acc[1][3] += a1 * b4.w;
            acc[2][0] += a2 * b4.x; acc[2][1] += a2 * b4.y; acc[2][2] += a2 * b4.z; acc[2][3] += a2 * b4.w;
            acc[3][0] += a3 * b4.x; acc[3][1] += a3 * b4.y; acc[3][2] += a3 * b4.z; acc[3][3] += a3 * b4.w;
        }
        __syncthreads();
    }

    if (MODE == 0 || MODE == 2) {
#pragma unroll
        for (int r = 0; r < 4; r++) {
            int m = m0 + ty * 4 + r;
#pragma unroll
            for (int c = 0; c < 4; c++) {
                int n = n0 + tx * 4 + c;
                Cout[(size_t)m * N + n] = acc[r][c] + bias[n];
            }
        }
    } else {
        // n0 is 64-aligned: whole tile maps to one (which, head)
        int which = n0 >> 10;            // 0=q,1=k,2=v
        int h = (n0 & 1023) >> 6;
        float* dst = (which == 0) ? g_q : (which == 1) ? g_k : g_v;
#pragma unroll
        for (int r = 0; r < 4; r++) {
            int m = m0 + ty * 4 + r;
            int bb = m >> 11;            // /2048
            int t  = m & 2047;
#pragma unroll
            for (int c = 0; c < 4; c++) {
                int d = tx * 4 + c;
                dst[(((size_t)bb * Hh + h) * Tt + t) * DHd + d] =
                    acc[r][c] + bias[n0 + tx * 4 + c];
            }
        }
    }
}

// ---------------------------------------------------------------------------
// Flash attention, fp32. One CTA = one (b,h) x 64-query block.
// S tile: rows -> ty (4 each), cols (keys) -> j = 16*c + tx (conflict-free KT reads)
// O tile: rows -> ty, cols (head dim) -> d = 4*tx + c
// ---------------------------------------------------------------------------
__global__ __launch_bounds__(256)
void attn_kernel()
{
    extern __shared__ float sm[];
    float* Qs = sm;                 // [64][65]  (i,d)
    float* KT = Qs + 64 * 65;       // [64][65]  (d,j)  transposed
    float* Ps = KT + 64 * 65;       // [64][65]  (i,j)
    float* Vs = Ps + 64 * 65;       // [64][64]  (j,d)

    const int tx = threadIdx.x, ty = threadIdx.y;
    const int tid = ty * 16 + tx;
    const int bh = blockIdx.y;
    const int q0 = blockIdx.x * 64;

    const float* qp = g_q + (size_t)bh * Tt * DHd + (size_t)q0 * DHd;
    const float* kp = g_k + (size_t)bh * Tt * DHd;
    const float* vp = g_v + (size_t)bh * Tt * DHd;

    // Load Q tile (64x64)
    for (int idx = tid; idx < 64 * 16; idx += 256) {
        int row = idx >> 4, c4 = (idx & 15) * 4;
        float4 v = *(const float4*)(qp + row * 64 + c4);
        Qs[row * 65 + c4 + 0] = v.x;
        Qs[row * 65 + c4 + 1] = v.y;
        Qs[row * 65 + c4 + 2] = v.z;
        Qs[row * 65 + c4 + 3] = v.w;
    }

    float mrow[4], lrow[4], o[4][4];
#pragma unroll
    for (int r = 0; r < 4; r++) {
        mrow[r] = -1e30f; lrow[r] = 0.0f;
#pragma unroll
        for (int c = 0; c < 4; c++) o[r][c] = 0.0f;
    }
    __syncthreads();

    const float scale = 0.125f;  // 1/sqrt(64)

    for (int kb = 0; kb < Tt / 64; kb++) {
        const float* kt = kp + (size_t)kb * 64 * DHd;
        const float* vt = vp + (size_t)kb * 64 * DHd;
        // Load K (transposed) and V tiles
        for (int idx = tid; idx < 64 * 16; idx += 256) {
            int row = idx >> 4, c4 = (idx & 15) * 4;
            float4 kv = *(const float4*)(kt + row * 64 + c4);
            KT[(c4 + 0) * 65 + row] = kv.x;
            KT[(c4 + 1) * 65 + row] = kv.y;
            KT[(c4 + 2) * 65 + row] = kv.z;
            KT[(c4 + 3) * 65 + row] = kv.w;
            float4 vv = *(const float4*)(vt + row * 64 + c4);
            *(float4*)(Vs + row * 64 + c4) = vv;
        }
        __syncthreads();

        // S = Q @ K^T * scale   (thread: rows ty*4+r, keys j = 16c+tx)
        float s[4][4];
#pragma unroll
        for (int r = 0; r < 4; r++)
#pragma unroll
            for (int c = 0; c < 4; c++) s[r][c] = 0.0f;

#pragma unroll 8
        for (int d = 0; d < 64; d++) {
            float a0 = Qs[(ty * 4 + 0) * 65 + d];
            float a1 = Qs[(ty * 4 + 1) * 65 + d];
            float a2 = Qs[(ty * 4 + 2) * 65 + d];
            float a3 = Qs[(ty * 4 + 3) * 65 + d];
            float k0v = KT[d * 65 + tx +  0];
            float k1v = KT[d * 65 + tx + 16];
            float k2v = KT[d * 65 + tx + 32];
            float k3v = KT[d * 65 + tx + 48];
            s[0][0] += a0 * k0v; s[0][1] += a0 * k1v; s[0][2] += a0 * k2v; s[0][3] += a0 * k3v;
            s[1][0] += a1 * k0v; s[1][1] += a1 * k1v; s[1][2] += a1 * k2v; s[1][3] += a1 * k3v;
            s[2][0] += a2 * k0v; s[2][1] += a2 * k1v; s[2][2] += a2 * k2v; s[2][3] += a2 * k3v;
            s[3][0] += a3 * k0v; s[3][1] += a3 * k1v; s[3][2] += a3 * k2v; s[3][3] += a3 * k3v;
        }

        // Online softmax per row (16 lanes per row, xor-shuffle within half-warp)
#pragma unroll
        for (int r = 0; r < 4; r++) {
            float mx = -1e30f;
#pragma unroll
            for (int c = 0; c < 4; c++) { s[r][c] *= scale; mx = fmaxf(mx, s[r][c]); }
#pragma unroll
            for (int off = 8; off >= 1; off >>= 1)
                mx = fmaxf(mx, __shfl_xor_sync(0xffffffffu, mx, off));
            float mnew = fmaxf(mrow[r], mx);
            float corr = __expf(mrow[r] - mnew);
            mrow[r] = mnew;
            float rs = 0.0f;
#pragma unroll
            for (int c = 0; c < 4; c++) { s[r][c] = __expf(s[r][c] - mnew); rs += s[r][c]; }
#pragma unroll
            for (int off = 8; off >= 1; off >>= 1)
                rs += __shfl_xor_sync(0xffffffffu, rs, off);
            lrow[r] = lrow[r] * corr + rs;
#pragma unroll
            for (int c = 0; c < 4; c++) {
                o[r][c] *= corr;
                Ps[(ty * 4 + r) * 65 + tx + 16 * c] = s[r][c];
            }
        }
        __syncthreads();

        // O += P @ V   (thread: rows ty*4+r, dims d = 4tx+c)
#pragma unroll 8
        for (int j = 0; j < 64; j++) {
            float p0 = Ps[(ty * 4 + 0) * 65 + j];
            float p1 = Ps[(ty * 4 + 1) * 65 + j];
            float p2 = Ps[(ty * 4 + 2) * 65 + j];
            float p3 = Ps[(ty * 4 + 3) * 65 + j];
            float4 vv = *(const float4*)(Vs + j * 64 + tx * 4);
            o[0][0] += p0 * vv.x; o[0][1] += p0 * vv.y; o[0][2] += p0 * vv.z; o[0][3] += p0 * vv.w;
            o[1][0] += p1 * vv.x; o[1][1] += p1 * vv.y; o[1][2] += p1 * vv.z; o[1][3] += p1 * vv.w;
            o[2][0] += p2 * vv.x; o[2][1] += p2 * vv.y; o[2][2] += p2 * vv.z; o[2][3] += p2 * vv.w;
            o[3][0] += p3 * vv.x; o[3][1] += p3 * vv.y; o[3][2] += p3 * vv.z; o[3][3] += p3 * vv.w;
        }
        __syncthreads();
    }

    // Epilogue: normalize and write to g_att[B,T,C]
    const int bb = bh >> 4, h = bh & 15;
#pragma unroll
    for (int r = 0; r < 4; r++) {
        int t = q0 + ty * 4 + r;
        float inv = 1.0f / lrow[r];
#pragma unroll
        for (int c = 0; c < 4; c++) {
            g_att[((size_t)bb * Tt + t) * Cc + h * 64 + tx * 4 + c] = o[r][c] * inv;
        }
    }
}

// ---------------------------------------------------------------------------
extern "C" void kernel_launch(void* const* d_in, const int* in_sizes, int n_in,
                              void* d_out, int out_size)
{
    const float* x      = (const float*)d_in[0];
    const float* W_qkv  = (const float*)d_in[1];
    const float* b_qkv  = (const float*)d_in[2];
    const float* W_proj = (const float*)d_in[3];
    const float* b_proj = (const float*)d_in[4];
    float* out = (float*)d_out;

    const int ATTN_SMEM = (64 * 65 * 3 + 64 * 64) * sizeof(float);  // 66304 B
    static bool attr_set = false;
    if (!attr_set) {
        cudaFuncSetAttribute(attn_kernel, cudaFuncAttributeMaxDynamicSharedMemorySize, ATTN_SMEM);
        attr_set = true;
    }

    dim3 blk(16, 16);
    // QKV: [4096,1024] @ [1024,3072] -> q/k/v scatter
    gemm_kernel<1><<<dim3(48, 64), blk>>>(x, W_qkv, b_qkv, nullptr, 3 * Cc);
    // Attention: 32 q-blocks x 32 (b,h)
    attn_kernel<<<dim3(Tt / 64, Bsz * Hh), blk, ATTN_SMEM>>>();
    // Proj: [4096,1024] @ [1024,1024] + bias -> out
    gemm_kernel<2><<<dim3(16, 64), blk>>>(nullptr, W_proj, b_proj, out, Cc);
}

// round 4
// speedup vs baseline: 2.3739x; 2.3739x over previous
#include <cuda_runtime.h>
#include <math.h>

#define Bsz 2
#define Tt  2048
#define Cc  1024
#define Hh  16
#define DHd 64

// Scratch (allocation-free: __device__ globals)
__device__ float g_q[(size_t)Bsz*Hh*Tt*DHd];   // [B,H,T,Dh]
__device__ float g_k[(size_t)Bsz*Hh*Tt*DHd];
__device__ float g_v[(size_t)Bsz*Hh*Tt*DHd];
__device__ float g_att[(size_t)Bsz*Tt*Cc];     // [B,T,C]

__device__ __forceinline__ unsigned f2tf(float f) {
    unsigned u;
    asm("cvt.rna.tf32.f32 %0, %1;" : "=r"(u) : "f"(f));
    return u;
}

__device__ __forceinline__ void mma_tf32(float c[4],
    unsigned a0, unsigned a1, unsigned a2, unsigned a3,
    unsigned b0, unsigned b1)
{
    asm volatile(
        "mma.sync.aligned.m16n8k8.row.col.f32.tf32.tf32.f32 "
        "{%0,%1,%2,%3}, {%4,%5,%6,%7}, {%8,%9}, {%0,%1,%2,%3};"
        : "+f"(c[0]), "+f"(c[1]), "+f"(c[2]), "+f"(c[3])
        : "r"(a0), "r"(a1), "r"(a2), "r"(a3), "r"(b0), "r"(b1));
}

// ---------------------------------------------------------------------------
// TF32 tensor-core GEMM: C[M,N] = A[M,1024] @ B[1024,N] + bias
// CTA tile 128x128, BK=32, 256 threads = 8 warps (4m x 2n), warp tile 32x64.
// MODE 1: scatter into g_q/g_k/g_v   MODE 2: A = g_att, write Cout
// ---------------------------------------------------------------------------
template <int MODE>
__global__ __launch_bounds__(256)
void gemm_tc(const float* __restrict__ A, const float* __restrict__ Bw,
             const float* __restrict__ bias, float* __restrict__ Cout, int N)
{
    __shared__ unsigned As[128 * 36];   // [m][k], pitch 36 -> conflict-free A frags
    __shared__ unsigned Bs[32 * 132];   // [k][n], pitch 132 -> conflict-free B frags

    const float* Aptr = (MODE == 2) ? g_att : A;

    const int tid = threadIdx.x;
    const int wid = tid >> 5, lane = tid & 31;
    const int group = lane >> 2, tig = lane & 3;
    const int mw = (wid & 3) * 32;      // warp m offset in tile
    const int nw = (wid >> 2) * 64;     // warp n offset in tile
    const int m0 = blockIdx.y * 128, n0 = blockIdx.x * 128;

    float acc[2][8][4];
#pragma unroll
    for (int mt = 0; mt < 2; mt++)
#pragma unroll
        for (int nt = 0; nt < 8; nt++)
#pragma unroll
            for (int c = 0; c < 4; c++) acc[mt][nt][c] = 0.0f;

    const int ar = tid >> 3;           // 0..31 (+32 strides)
    const int ak = (tid & 7) * 4;      // 0..28
    const int br = tid >> 5;           // 0..7 (+8 strides)
    const int bn = (tid & 31) * 4;     // 0..124

    for (int k0 = 0; k0 < 1024; k0 += 32) {
#pragma unroll
        for (int i = 0; i < 4; i++) {
            int m = ar + i * 32;
            float4 v = *(const float4*)(Aptr + (size_t)(m0 + m) * 1024 + k0 + ak);
            As[m * 36 + ak + 0] = f2tf(v.x);
            As[m * 36 + ak + 1] = f2tf(v.y);
            As[m * 36 + ak + 2] = f2tf(v.z);
            As[m * 36 + ak + 3] = f2tf(v.w);
        }
#pragma unroll
        for (int i = 0; i < 4; i++) {
            int kk = br + i * 8;
            float4 v = *(const float4*)(Bw + (size_t)(k0 + kk) * N + n0 + bn);
            Bs[kk * 132 + bn + 0] = f2tf(v.x);
            Bs[kk * 132 + bn + 1] = f2tf(v.y);
            Bs[kk * 132 + bn + 2] = f2tf(v.z);
            Bs[kk * 132 + bn + 3] = f2tf(v.w);
        }
        __syncthreads();

#pragma unroll
        for (int ks = 0; ks < 4; ks++) {
            unsigned a[2][4];
#pragma unroll
            for (int mt = 0; mt < 2; mt++) {
                int row = mw + mt * 16 + group;
                a[mt][0] = As[row * 36 + ks * 8 + tig];
                a[mt][1] = As[(row + 8) * 36 + ks * 8 + tig];
                a[mt][2] = As[row * 36 + ks * 8 + tig + 4];
                a[mt][3] = As[(row + 8) * 36 + ks * 8 + tig + 4];
            }
#pragma unroll
            for (int nt = 0; nt < 8; nt++) {
                unsigned b0 = Bs[(ks * 8 + tig) * 132 + nw + nt * 8 + group];
                unsigned b1 = Bs[(ks * 8 + tig + 4) * 132 + nw + nt * 8 + group];
#pragma unroll
                for (int mt = 0; mt < 2; mt++)
                    mma_tf32(acc[mt][nt], a[mt][0], a[mt][1], a[mt][2], a[mt][3], b0, b1);
            }
        }
        __syncthreads();
    }

    // Epilogue
#pragma unroll
    for (int mt = 0; mt < 2; mt++) {
        int mrow0 = m0 + mw + mt * 16 + group;
#pragma unroll
        for (int nt = 0; nt < 8; nt++) {
#pragma unroll
            for (int c = 0; c < 4; c++) {
                int m = mrow0 + (c >= 2 ? 8 : 0);
                int n = n0 + nw + nt * 8 + 2 * tig + (c & 1);
                float val = acc[mt][nt][c] + bias[n];
                if (MODE == 2) {
                    Cout[(size_t)m * N + n] = val;
                } else {
                    int which = n >> 10;
                    int h = (n >> 6) & 15;
                    int d = n & 63;
                    int bb = m >> 11, t = m & 2047;
                    float* dst = (which == 0) ? g_q : (which == 1) ? g_k : g_v;
                    dst[(((size_t)bb * Hh + h) * Tt + t) * DHd + d] = val;
                }
            }
        }
    }
}

// ---------------------------------------------------------------------------
// TF32 flash attention. CTA = (b,h) x 64-query block, 4 warps (16 q-rows each).
// Q fragments register-resident; online softmax in mma accumulator layout;
// P restaged through warp-private padded smem for the PV mma.
// ---------------------------------------------------------------------------
__global__ __launch_bounds__(128)
void attn_tc()
{
    extern __shared__ unsigned smu[];
    unsigned* KTs = smu;                 // [64 d][72]  (K transposed, tf32 bits)
    unsigned* Vs  = smu + 64 * 72;       // [64 j][72]
    unsigned* Ps  = smu + 2 * 64 * 72;   // per-warp [16][72]

    const int tid = threadIdx.x;
    const int wid = tid >> 5, lane = tid & 31;
    const int group = lane >> 2, tig = lane & 3;
    const int bh = blockIdx.y, q0 = blockIdx.x * 64;

    const float* qp = g_q + (size_t)bh * Tt * DHd;
    const float* kp = g_k + (size_t)bh * Tt * DHd;
    const float* vp = g_v + (size_t)bh * Tt * DHd;
    unsigned* Pw = Ps + wid * 16 * 72;

    // Q fragments (rows q0+wid*16+group, +8), resident for whole kernel
    unsigned qf[8][4];
    const int qrow = q0 + wid * 16 + group;
#pragma unroll
    for (int ks = 0; ks < 8; ks++) {
        qf[ks][0] = f2tf(qp[(size_t)qrow * 64 + ks * 8 + tig]);
        qf[ks][1] = f2tf(qp[(size_t)(qrow + 8) * 64 + ks * 8 + tig]);
        qf[ks][2] = f2tf(qp[(size_t)qrow * 64 + ks * 8 + tig + 4]);
        qf[ks][3] = f2tf(qp[(size_t)(qrow + 8) * 64 + ks * 8 + tig + 4]);
    }

    float o[8][4];
#pragma unroll
    for (int nt = 0; nt < 8; nt++)
#pragma unroll
        for (int c = 0; c < 4; c++) o[nt][c] = 0.0f;
    float mrow[2] = {-1e30f, -1e30f};
    float lrow[2] = {0.0f, 0.0f};

    for (int kb = 0; kb < Tt / 64; kb++) {
        const float* kt = kp + (size_t)kb * 64 * DHd;
        const float* vt = vp + (size_t)kb * 64 * DHd;
        for (int idx = tid; idx < 64 * 16; idx += 128) {
            int row = idx >> 4, c4 = (idx & 15) * 4;
            float4 kv = *(const float4*)(kt + row * 64 + c4);
            KTs[(c4 + 0) * 72 + row] = f2tf(kv.x);
            KTs[(c4 + 1) * 72 + row] = f2tf(kv.y);
            KTs[(c4 + 2) * 72 + row] = f2tf(kv.z);
            KTs[(c4 + 3) * 72 + row] = f2tf(kv.w);
            float4 vv = *(const float4*)(vt + row * 64 + c4);
            Vs[row * 72 + c4 + 0] = f2tf(vv.x);
            Vs[row * 72 + c4 + 1] = f2tf(vv.y);
            Vs[row * 72 + c4 + 2] = f2tf(vv.z);
            Vs[row * 72 + c4 + 3] = f2tf(vv.w);
        }
        __syncthreads();

        // S = Q @ K^T  (per warp: 16 x 64)
        float s[8][4];
#pragma unroll
        for (int nt = 0; nt < 8; nt++)
#pragma unroll
            for (int c = 0; c < 4; c++) s[nt][c] = 0.0f;
#pragma unroll
        for (int ks = 0; ks < 8; ks++) {
#pragma unroll
            for (int nt = 0; nt < 8; nt++) {
                unsigned b0 = KTs[(ks * 8 + tig) * 72 + nt * 8 + group];
                unsigned b1 = KTs[(ks * 8 + tig + 4) * 72 + nt * 8 + group];
                mma_tf32(s[nt], qf[ks][0], qf[ks][1], qf[ks][2], qf[ks][3], b0, b1);
            }
        }

        // Online softmax. Thread rows: group (c 0,1) and group+8 (c 2,3).
        float mx0 = -1e30f, mx1 = -1e30f;
#pragma unroll
        for (int nt = 0; nt < 8; nt++) {
            s[nt][0] *= 0.125f; s[nt][1] *= 0.125f;
            s[nt][2] *= 0.125f; s[nt][3] *= 0.125f;
            mx0 = fmaxf(mx0, fmaxf(s[nt][0], s[nt][1]));
            mx1 = fmaxf(mx1, fmaxf(s[nt][2], s[nt][3]));
        }
        mx0 = fmaxf(mx0, __shfl_xor_sync(0xffffffffu, mx0, 1));
        mx0 = fmaxf(mx0, __shfl_xor_sync(0xffffffffu, mx0, 2));
        mx1 = fmaxf(mx1, __shfl_xor_sync(0xffffffffu, mx1, 1));
        mx1 = fmaxf(mx1, __shfl_xor_sync(0xffffffffu, mx1, 2));
        float mn0 = fmaxf(mrow[0], mx0), mn1 = fmaxf(mrow[1], mx1);
        float cr0 = __expf(mrow[0] - mn0), cr1 = __expf(mrow[1] - mn1);
        mrow[0] = mn0; mrow[1] = mn1;
        float rs0 = 0.0f, rs1 = 0.0f;
#pragma unroll
        for (int nt = 0; nt < 8; nt++) {
            s[nt][0] = __expf(s[nt][0] - mn0);
            s[nt][1] = __expf(s[nt][1] - mn0);
            s[nt][2] = __expf(s[nt][2] - mn1);
            s[nt][3] = __expf(s[nt][3] - mn1);
            rs0 += s[nt][0] + s[nt][1];
            rs1 += s[nt][2] + s[nt][3];
        }
        rs0 += __shfl_xor_sync(0xffffffffu, rs0, 1);
        rs0 += __shfl_xor_sync(0xffffffffu, rs0, 2);
        rs1 += __shfl_xor_sync(0xffffffffu, rs1, 1);
        rs1 += __shfl_xor_sync(0xffffffffu, rs1, 2);
        lrow[0] = lrow[0] * cr0 + rs0;
        lrow[1] = lrow[1] * cr1 + rs1;

        // Rescale O, stage P (C-layout -> smem) for the PV mma A-fragments
#pragma unroll
        for (int nt = 0; nt < 8; nt++) {
            o[nt][0] *= cr0; o[nt][1] *= cr0;
            o[nt][2] *= cr1; o[nt][3] *= cr1;
            Pw[group * 72 + nt * 8 + 2 * tig + 0] = f2tf(s[nt][0]);
            Pw[group * 72 + nt * 8 + 2 * tig + 1] = f2tf(s[nt][1]);
            Pw[(group + 8) * 72 + nt * 8 + 2 * tig + 0] = f2tf(s[nt][2]);
            Pw[(group + 8) * 72 + nt * 8 + 2 * tig + 1] = f2tf(s[nt][3]);
        }
        __syncwarp();

        // O += P @ V
#pragma unroll
        for (int ks = 0; ks < 8; ks++) {
            unsigned a0 = Pw[group * 72 + ks * 8 + tig];
            unsigned a1 = Pw[(group + 8) * 72 + ks * 8 + tig];
            unsigned a2 = Pw[group * 72 + ks * 8 + tig + 4];
            unsigned a3 = Pw[(group + 8) * 72 + ks * 8 + tig + 4];
#pragma unroll
            for (int nt = 0; nt < 8; nt++) {
                unsigned b0 = Vs[(ks * 8 + tig) * 72 + nt * 8 + group];
                unsigned b1 = Vs[(ks * 8 + tig + 4) * 72 + nt * 8 + group];
                mma_tf32(o[nt], a0, a1, a2, a3, b0, b1);
            }
        }
        __syncthreads();
    }

    // Epilogue: normalize, write g_att[B,T,C]
    const int bb = bh >> 4, h = bh & 15;
    const float inv0 = 1.0f / lrow[0], inv1 = 1.0f / lrow[1];
    const int t0 = q0 + wid * 16 + group;
#pragma unroll
    for (int nt = 0; nt < 8; nt++) {
        int d = h * 64 + nt * 8 + 2 * tig;
        g_att[((size_t)bb * Tt + t0) * Cc + d + 0] = o[nt][0] * inv0;
        g_att[((size_t)bb * Tt + t0) * Cc + d + 1] = o[nt][1] * inv0;
        g_att[((size_t)bb * Tt + t0 + 8) * Cc + d + 0] = o[nt][2] * inv1;
        g_att[((size_t)bb * Tt + t0 + 8) * Cc + d + 1] = o[nt][3] * inv1;
    }
}

// ---------------------------------------------------------------------------
extern "C" void kernel_launch(void* const* d_in, const int* in_sizes, int n_in,
                              void* d_out, int out_size)
{
    const float* x      = (const float*)d_in[0];
    const float* W_qkv  = (const float*)d_in[1];
    const float* b_qkv  = (const float*)d_in[2];
    const float* W_proj = (const float*)d_in[3];
    const float* b_proj = (const float*)d_in[4];
    float* out = (float*)d_out;

    const int ATTN_SMEM = (2 * 64 * 72 + 4 * 16 * 72) * sizeof(unsigned);  // 55296 B
    cudaFuncSetAttribute(attn_tc, cudaFuncAttributeMaxDynamicSharedMemorySize, ATTN_SMEM);

    // QKV: [4096,1024] @ [1024,3072] -> q/k/v scatter
    gemm_tc<1><<<dim3(24, 32), 256>>>(x, W_qkv, b_qkv, nullptr, 3 * Cc);
    // Attention: 32 q-blocks x 32 (b,h)
    attn_tc<<<dim3(Tt / 64, Bsz * Hh), 128, ATTN_SMEM>>>();
    // Proj: [4096,1024] @ [1024,1024] + bias
    gemm_tc<2><<<dim3(8, 32), 256>>>(nullptr, W_proj, b_proj, out, Cc);
}

// round 5
// speedup vs baseline: 4.1680x; 1.7557x over previous
#include <cuda_runtime.h>
#include <math.h>

#define Bsz 2
#define Tt  2048
#define Cc  1024
#define Hh  16
#define DHd 64

// ---------------- fragment-layout scratch (tf32 bits) ----------------------
// A-frag layout: [rb = m/16][kg = k/8][lane 32][reg 4]
// B-frag layout: [kg = k/8][nb = n/8][lane 32][reg 2]
// K per-(bh,kb) B-frag slice: [bh][kb][kg_d 8][nb_j 8][lane][2] (16KB/slice)
// V per-(bh,kb) B-frag slice: [bh][kb][kg_j 8][nb_d 8][lane][2]
__device__ unsigned g_xfrag[(size_t)256 * 128 * 128];      // x  A-frag
__device__ unsigned g_wqkv [(size_t)128 * 384 * 64];       // W_qkv B-frag
__device__ unsigned g_wproj[(size_t)128 * 128 * 64];       // W_proj B-frag
__device__ unsigned g_q    [(size_t)32 * 128 * 8 * 128];   // Q A-frag per bh
__device__ unsigned g_k    [(size_t)32 * 32 * 4096];       // K B-frag slices
__device__ unsigned g_v    [(size_t)32 * 32 * 4096];       // V B-frag slices
__device__ unsigned g_attf [(size_t)256 * 128 * 128];      // attn out A-frag

__device__ __forceinline__ unsigned f2tf(float f) {
    unsigned u;
    asm("cvt.rna.tf32.f32 %0, %1;" : "=r"(u) : "f"(f));
    return u;
}

__device__ __forceinline__ void mma_tf32(float c[4],
    unsigned a0, unsigned a1, unsigned a2, unsigned a3,
    unsigned b0, unsigned b1)
{
    asm volatile(
        "mma.sync.aligned.m16n8k8.row.col.f32.tf32.tf32.f32 "
        "{%0,%1,%2,%3}, {%4,%5,%6,%7}, {%8,%9}, {%0,%1,%2,%3};"
        : "+f"(c[0]), "+f"(c[1]), "+f"(c[2]), "+f"(c[3])
        : "r"(a0), "r"(a1), "r"(a2), "r"(a3), "r"(b0), "r"(b1));
}

__device__ __forceinline__ void cpa16(unsigned dst, const void* src) {
    asm volatile("cp.async.cg.shared.global [%0], [%1], 16;" :: "r"(dst), "l"(src));
}
#define CP_COMMIT()  asm volatile("cp.async.commit_group;")
#define CP_WAIT0()   asm volatile("cp.async.wait_group 0;")
#define CP_WAIT1()   asm volatile("cp.async.wait_group 1;")

// ---------------------------------------------------------------------------
// Prep: convert inputs to tf32 fragment layouts
// ---------------------------------------------------------------------------
__global__ __launch_bounds__(256) void prep_x_k(const float* __restrict__ x)
{
    int idx = blockIdx.x * 256 + threadIdx.x;       // 4096*256 float4s
    int m = idx >> 8, k4 = (idx & 255) << 2;
    float4 v = *(const float4*)(x + (size_t)m * 1024 + k4);
    unsigned r = ((m >> 3) & 1) | (((k4 >> 2) & 1) << 1);
    size_t b = (((size_t)(m >> 4) * 128 + (k4 >> 3)) * 32) * 4 + ((m & 7) << 4) + r;
    g_xfrag[b + 0]  = f2tf(v.x);
    g_xfrag[b + 4]  = f2tf(v.y);
    g_xfrag[b + 8]  = f2tf(v.z);
    g_xfrag[b + 12] = f2tf(v.w);
}

__global__ __launch_bounds__(256) void prep_w_k(const float* __restrict__ W, int N, int sel)
{
    unsigned* dst = sel ? g_wproj : g_wqkv;
    int NB = N >> 3;
    int idx = blockIdx.x * 256 + threadIdx.x;       // 1024*(N/4) float4s
    int k = idx / (N >> 2), n4 = (idx % (N >> 2)) << 2;
    float4 v = *(const float4*)(W + (size_t)k * N + n4);
    unsigned r = (k >> 2) & 1;
    size_t b = ((size_t)(k >> 3) * NB + (n4 >> 3)) * 64 + ((n4 & 7) * 4 + (k & 3)) * 2 + r;
    dst[b + 0]  = f2tf(v.x);
    dst[b + 8]  = f2tf(v.y);
    dst[b + 16] = f2tf(v.z);
    dst[b + 24] = f2tf(v.w);
}

// ---------------------------------------------------------------------------
// TF32 GEMM on fragment layouts. CTA 128x128, BK=32, 8 warps, double-buffered
// cp.async smem. MODE 1: A=g_xfrag, B=g_wqkv, scatter q/k/v frag layouts.
// MODE 2: A=g_attf, B=g_wproj, write float out + bias.
// ---------------------------------------------------------------------------
template <int MODE>
__global__ __launch_bounds__(256)
void gemm_tc(const float* __restrict__ bias, float* __restrict__ Cout, int N)
{
    extern __shared__ unsigned smg[];
    unsigned* As = smg;            // 2 x 4096 words
    unsigned* Bs = smg + 8192;     // 2 x 4096 words
    const unsigned* Af = (MODE == 1) ? g_xfrag : g_attf;
    const unsigned* Bf = (MODE == 1) ? g_wqkv  : g_wproj;
    const int NB = N >> 3;

    const int tid = threadIdx.x, wid = tid >> 5, lane = tid & 31;
    const int group = lane >> 2, tig = lane & 3;
    const int mw = (wid & 3) * 32, nw = (wid >> 2) * 64;
    const int m0 = blockIdx.y * 128, n0 = blockIdx.x * 128;
    const int rb0 = m0 >> 4, nb0 = n0 >> 3;

    unsigned sbase = (unsigned)__cvta_generic_to_shared(smg);
    unsigned sA = sbase, sB = sbase + 32768;

    float acc[2][8][4] = {};

#define COPY_CHUNK(cidx, buf)                                                      \
    {                                                                              \
        int kg0 = (cidx) * 4;                                                      \
        _Pragma("unroll")                                                          \
        for (int l = 0; l < 4; l++) {                                              \
            int w = (tid + l * 256) * 4;                                           \
            int rb = w >> 9, rem = w & 511;                                        \
            cpa16(sA + (buf) * 16384 + w * 4,                                      \
                  Af + (size_t)(rb0 + rb) * 16384 + kg0 * 128 + rem);              \
            int kgl = w >> 10, rem2 = w & 1023;                                    \
            cpa16(sB + (buf) * 16384 + w * 4,                                      \
                  Bf + (size_t)(kg0 + kgl) * NB * 64 + nb0 * 64 + rem2);           \
        }                                                                          \
    }

    COPY_CHUNK(0, 0); CP_COMMIT();

    for (int c = 0; c < 32; c++) {
        int buf = c & 1;
        __syncthreads();                       // readers of buf^1 (iter c-1) done
        if (c + 1 < 32) { COPY_CHUNK(c + 1, buf ^ 1); CP_COMMIT(); CP_WAIT1(); }
        else           { CP_WAIT0(); }
        __syncthreads();                       // chunk c visible to all

#pragma unroll
        for (int ks = 0; ks < 4; ks++) {
            uint4 a[2];
#pragma unroll
            for (int mt = 0; mt < 2; mt++) {
                int rbl = (wid & 3) * 2 + mt;
                a[mt] = *(const uint4*)(As + buf * 4096 + ((rbl * 4 + ks) * 32 + lane) * 4);
            }
#pragma unroll
            for (int nt = 0; nt < 8; nt++) {
                uint2 b = *(const uint2*)(Bs + buf * 4096 + ((ks * 16 + (nw >> 3) + nt) * 32 + lane) * 2);
                mma_tf32(acc[0][nt], a[0].x, a[0].y, a[0].z, a[0].w, b.x, b.y);
                mma_tf32(acc[1][nt], a[1].x, a[1].y, a[1].z, a[1].w, b.x, b.y);
            }
        }
    }
#undef COPY_CHUNK

#pragma unroll
    for (int mt = 0; mt < 2; mt++) {
#pragma unroll
        for (int nt = 0; nt < 8; nt++) {
#pragma unroll
            for (int cc = 0; cc < 4; cc++) {
                int m = m0 + mw + mt * 16 + group + ((cc >> 1) << 3);
                int n = n0 + nw + nt * 8 + 2 * tig + (cc & 1);
                float val = acc[mt][nt][cc] + bias[n];
                if (MODE == 2) {
                    Cout[(size_t)m * Cc + n] = val;
                } else {
                    int which = n >> 10, h = (n >> 6) & 15, d = n & 63;
                    int bb = m >> 11, t = m & 2047;
                    int bh = bb * 16 + h;
                    if (which == 0) {
                        // fold 1/sqrt(Dh)=0.125 into Q (exact power of 2)
                        unsigned u = f2tf(val * 0.125f);
                        size_t idx = (((size_t)(bh * 128 + (t >> 4)) * 8 + (d >> 3)) * 32
                                      + (t & 7) * 4 + (d & 3)) * 4
                                     + ((t >> 3) & 1) + (((d >> 2) & 1) << 1);
                        g_q[idx] = u;
                    } else if (which == 1) {
                        unsigned u = f2tf(val);
                        size_t idx = (((size_t)(bh * 32 + (t >> 6)) * 8 + (d >> 3)) * 8
                                      + ((t >> 3) & 7)) * 64
                                     + ((t & 7) * 4 + (d & 3)) * 2 + ((d >> 2) & 1);
                        g_k[idx] = u;
                    } else {
                        unsigned u = f2tf(val);
                        size_t idx = (((size_t)(bh * 32 + (t >> 6)) * 8 + ((t >> 3) & 7)) * 8
                                      + (d >> 3)) * 64
                                     + ((d & 7) * 4 + (t & 3)) * 2 + ((t >> 2) & 1);
                        g_v[idx] = u;
                    }
                }
            }
        }
    }
}

// ---------------------------------------------------------------------------
// TF32 flash attention on fragment layouts. CTA = (b,h) x 64 q-rows, 4 warps.
// K/V arrive pre-converted + pre-swizzled: smem fill is a pure cp.async copy.
// ---------------------------------------------------------------------------
__global__ __launch_bounds__(128)
void attn_tc()
{
    extern __shared__ unsigned smu[];
    unsigned* Kf = smu;              // 4096 words
    unsigned* Vf = smu + 4096;       // 4096 words
    unsigned* Ps = smu + 8192;       // 4 * 16 * 72 words

    const int tid = threadIdx.x, wid = tid >> 5, lane = tid & 31;
    const int group = lane >> 2, tig = lane & 3;
    const int bh = blockIdx.y, q0 = blockIdx.x * 64;
    unsigned* Pw = Ps + wid * 16 * 72;

    unsigned sbase = (unsigned)__cvta_generic_to_shared(smu);
    unsigned sK = sbase, sV = sbase + 16384;

    // Q A-fragments: 8 LDG.128, resident all kernel (pre-scaled by 0.125)
    uint4 qf[8];
    const unsigned* qbase = g_q + (size_t)(bh * 128 + (q0 >> 4) + wid) * 8 * 128;
#pragma unroll
    for (int kg = 0; kg < 8; kg++)
        qf[kg] = *(const uint4*)(qbase + kg * 128 + lane * 4);

    float o[8][4] = {};
    float mrow[2] = {-1e30f, -1e30f};
    float lrow[2] = {0.0f, 0.0f};

    const unsigned* kbp = g_k + (size_t)bh * 32 * 4096;
    const unsigned* vbp = g_v + (size_t)bh * 32 * 4096;

    for (int kb = 0; kb < 32; kb++) {
#pragma unroll
        for (int l = 0; l < 8; l++) {
            int w = (tid + l * 128) * 4;
            cpa16(sK + w * 4, kbp + (size_t)kb * 4096 + w);
            cpa16(sV + w * 4, vbp + (size_t)kb * 4096 + w);
        }
        CP_COMMIT(); CP_WAIT0();
        __syncthreads();

        // S = Q @ K^T (pre-scaled)
        float s[8][4] = {};
#pragma unroll
        for (int ks = 0; ks < 8; ks++) {
#pragma unroll
            for (int nt = 0; nt < 8; nt++) {
                uint2 b = *(const uint2*)(Kf + ((ks * 8 + nt) * 32 + lane) * 2);
                mma_tf32(s[nt], qf[ks].x, qf[ks].y, qf[ks].z, qf[ks].w, b.x, b.y);
            }
        }

        // Online softmax (rows: group -> c0/c1, group+8 -> c2/c3)
        float mx0 = -1e30f, mx1 = -1e30f;
#pragma unroll
        for (int nt = 0; nt < 8; nt++) {
            mx0 = fmaxf(mx0, fmaxf(s[nt][0], s[nt][1]));
            mx1 = fmaxf(mx1, fmaxf(s[nt][2], s[nt][3]));
        }
        mx0 = fmaxf(mx0, __shfl_xor_sync(0xffffffffu, mx0, 1));
        mx0 = fmaxf(mx0, __shfl_xor_sync(0xffffffffu, mx0, 2));
        mx1 = fmaxf(mx1, __shfl_xor_sync(0xffffffffu, mx1, 1));
        mx1 = fmaxf(mx1, __shfl_xor_sync(0xffffffffu, mx1, 2));
        float mn0 = fmaxf(mrow[0], mx0), mn1 = fmaxf(mrow[1], mx1);
        float cr0 = __expf(mrow[0] - mn0), cr1 = __expf(mrow[1] - mn1);
        mrow[0] = mn0; mrow[1] = mn1;
        float rs0 = 0.0f, rs1 = 0.0f;
#pragma unroll
        for (int nt = 0; nt < 8; nt++) {
            s[nt][0] = __expf(s[nt][0] - mn0);
            s[nt][1] = __expf(s[nt][1] - mn0);
            s[nt][2] = __expf(s[nt][2] - mn1);
            s[nt][3] = __expf(s[nt][3] - mn1);
            rs0 += s[nt][0] + s[nt][1];
            rs1 += s[nt][2] + s[nt][3];
        }
        rs0 += __shfl_xor_sync(0xffffffffu, rs0, 1);
        rs0 += __shfl_xor_sync(0xffffffffu, rs0, 2);
        rs1 += __shfl_xor_sync(0xffffffffu, rs1, 1);
        rs1 += __shfl_xor_sync(0xffffffffu, rs1, 2);
        lrow[0] = lrow[0] * cr0 + rs0;
        lrow[1] = lrow[1] * cr1 + rs1;

        // Rescale O; stage P for PV A-fragments (conflict-free, pitch 72)
#pragma unroll
        for (int nt = 0; nt < 8; nt++) {
            o[nt][0] *= cr0; o[nt][1] *= cr0;
            o[nt][2] *= cr1; o[nt][3] *= cr1;
            Pw[group * 72 + nt * 8 + 2 * tig + 0] = f2tf(s[nt][0]);
            Pw[group * 72 + nt * 8 + 2 * tig + 1] = f2tf(s[nt][1]);
            Pw[(group + 8) * 72 + nt * 8 + 2 * tig + 0] = f2tf(s[nt][2]);
            Pw[(group + 8) * 72 + nt * 8 + 2 * tig + 1] = f2tf(s[nt][3]);
        }
        __syncwarp();

        // O += P @ V
#pragma unroll
        for (int ks = 0; ks < 8; ks++) {
            unsigned a0 = Pw[group * 72 + ks * 8 + tig];
            unsigned a1 = Pw[(group + 8) * 72 + ks * 8 + tig];
            unsigned a2 = Pw[group * 72 + ks * 8 + tig + 4];
            unsigned a3 = Pw[(group + 8) * 72 + ks * 8 + tig + 4];
#pragma unroll
            for (int nt = 0; nt < 8; nt++) {
                uint2 b = *(const uint2*)(Vf + ((ks * 8 + nt) * 32 + lane) * 2);
                mma_tf32(o[nt], a0, a1, a2, a3, b.x, b.y);
            }
        }
        __syncthreads();
    }

    // Epilogue: normalize, write A-frag layout (tf32 bits) for proj GEMM
    const int bb = bh >> 4, h = bh & 15;
    const float inv0 = 1.0f / lrow[0], inv1 = 1.0f / lrow[1];
    const int ta = q0 + wid * 16 + group;
    const int rba = bb * 128 + (ta >> 4);
    const int laneb = group * 4 + 2 * (tig & 1);
    const int regb2 = (tig >> 1) << 1;
#pragma unroll
    for (int nt = 0; nt < 8; nt++) {
        int kg = h * 8 + nt;
        size_t base = ((size_t)rba * 128 + kg) * 128 + laneb * 4;
        g_attf[base + regb2 + 0]     = f2tf(o[nt][0] * inv0);
        g_attf[base + 4 + regb2 + 0] = f2tf(o[nt][1] * inv0);
        g_attf[base + regb2 + 1]     = f2tf(o[nt][2] * inv1);
        g_attf[base + 4 + regb2 + 1] = f2tf(o[nt][3] * inv1);
    }
}

// ---------------------------------------------------------------------------
extern "C" void kernel_launch(void* const* d_in, const int* in_sizes, int n_in,
                              void* d_out, int out_size)
{
    const float* x      = (const float*)d_in[0];
    const float* W_qkv  = (const float*)d_in[1];
    const float* b_qkv  = (const float*)d_in[2];
    const float* W_proj = (const float*)d_in[3];
    const float* b_proj = (const float*)d_in[4];
    float* out = (float*)d_out;

    const int GEMM_SMEM = 16384 * 4;                       // 64 KB
    const int ATTN_SMEM = (4096 + 4096 + 4 * 16 * 72) * 4; // 51200 B
    cudaFuncSetAttribute(gemm_tc<1>, cudaFuncAttributeMaxDynamicSharedMemorySize, GEMM_SMEM);
    cudaFuncSetAttribute(gemm_tc<2>, cudaFuncAttributeMaxDynamicSharedMemorySize, GEMM_SMEM);
    cudaFuncSetAttribute(attn_tc,    cudaFuncAttributeMaxDynamicSharedMemorySize, ATTN_SMEM);

    // Prep: inputs -> tf32 fragment layouts
    prep_x_k<<<4096, 256>>>(x);
    prep_w_k<<<3072, 256>>>(W_qkv, 3 * Cc, 0);
    prep_w_k<<<1024, 256>>>(W_proj, Cc, 1);

    // QKV GEMM -> q/k/v fragment layouts
    gemm_tc<1><<<dim3(24, 32), 256, GEMM_SMEM>>>(b_qkv, nullptr, 3 * Cc);
    // Attention
    attn_tc<<<dim3(32, 32), 128, ATTN_SMEM>>>();
    // Proj GEMM -> final out
    gemm_tc<2><<<dim3(8, 32), 256, GEMM_SMEM>>>(b_proj, out, Cc);
}